// round 16
// baseline (speedup 1.0000x reference)
#include <cuda_runtime.h>
#include <cuda_fp16.h>
#include <cstdint>

#define NROW 2048
#define DM   1152
#define SKV  256
#define HIDN 768
#define REG  288            // DM/4
#define HDM  (HIDN*DM)      // one expert matrix (either orientation)
#define KVLD 2304           // combined K|V row stride

// ---------------- scratch (device globals; allocation-free) ----------------
__device__ float g_q[NROW*DM];
__device__ float g_kv[SKV*KVLD];
__device__ float g_cap2[NROW*DM];
__device__ float g_caplog[NROW*4];
__device__ float g_aclog[NROW*4];
__device__ float g_hl[4];
__device__ float g_cm[NROW];
__device__ float g_am[NROW];
__device__ int   g_cpe[NROW];
__device__ int   g_ape[NROW];
__device__ int   g_cnt[8];
__device__ int   g_off[8];
__device__ int   g_idx[2*NROW];          // perm position -> original row
__device__ float g_H[4096L*1536];        // MoE up combined (h1|h3), perm order
__device__ float g_R[8192L*1536];        // region up combined
__device__ float g_y[NROW*DM];

// fp16 operands: activations hi/lo (A side), weights single fp16 (B side)
__device__ __half g_xh[NROW*DM],  g_xl[NROW*DM];
__device__ __half g_gxh[2*NROW*DM], g_gxl[2*NROW*DM];
__device__ __half g_caph[SKV*DM], g_capl[SKV*DM];
__device__ __half g_win16[3*DM*DM];
__device__ __half g_wout16[DM*DM];
__device__ __half g_ew16[36L*HDM];
__device__ __half g_cah[NROW*DM], g_cal[NROW*DM];
__device__ __half g_Hh[4096L*HIDN], g_Hl[4096L*HIDN];
__device__ __half g_yh[NROW*DM],  g_yl[NROW*DM];
__device__ __half g_Rh[8192L*HIDN], g_Rl[8192L*HIDN];

// ---------------- helpers ----------------
__device__ __forceinline__ uint32_t smem_to_u32(const void* p) {
    uint32_t a;
    asm("{ .reg .u64 t; cvta.to.shared.u64 t, %1; cvt.u32.u64 %0, t; }" : "=r"(a) : "l"(p));
    return a;
}

#define CPA(dst, src, sz) \
    asm volatile("cp.async.cg.shared.global [%0], [%1], 16, %2;" \
                 :: "r"(dst), "l"(src), "r"(sz) : "memory")
#define CPA_COMMIT() asm volatile("cp.async.commit_group;" ::: "memory")
#define CPA_WAIT0()  asm volatile("cp.async.wait_group 0;" ::: "memory")

#define LDSM4(r0, r1, r2, r3, addr) \
    asm volatile("ldmatrix.sync.aligned.m8n8.x4.shared.b16 {%0,%1,%2,%3}, [%4];" \
                 : "=r"(r0), "=r"(r1), "=r"(r2), "=r"(r3) : "r"(addr))

__device__ __forceinline__ void mma16f(float* d, const uint32_t* a, const uint32_t* b)
{
    asm volatile(
        "mma.sync.aligned.m16n8k16.row.col.f32.f16.f16.f32 "
        "{%0,%1,%2,%3}, {%4,%5,%6,%7}, {%8,%9}, {%0,%1,%2,%3};\n"
        : "+f"(d[0]), "+f"(d[1]), "+f"(d[2]), "+f"(d[3])
        : "r"(a[0]), "r"(a[1]), "r"(a[2]), "r"(a[3]), "r"(b[0]), "r"(b[1]));
}

// ---------------- threefry2x32-20 (exact JAX, partitionable) ----------------
__device__ __forceinline__ uint32_t rotl32(uint32_t v, int r){ return (v<<r)|(v>>(32-r)); }

__device__ __forceinline__ void tf2x32(uint32_t k0, uint32_t k1, uint32_t x0, uint32_t x1,
                                       uint32_t& o0, uint32_t& o1)
{
    uint32_t ks2 = k0 ^ k1 ^ 0x1BD11BDAu;
    x0 += k0; x1 += k1;
#define TFR(r) { x0 += x1; x1 = rotl32(x1,(r)); x1 ^= x0; }
    TFR(13) TFR(15) TFR(26) TFR(6)   x0 += k1;  x1 += ks2 + 1u;
    TFR(17) TFR(29) TFR(16) TFR(24)  x0 += ks2; x1 += k0  + 2u;
    TFR(13) TFR(15) TFR(26) TFR(6)   x0 += k0;  x1 += k1  + 3u;
    TFR(17) TFR(29) TFR(16) TFR(24)  x0 += k1;  x1 += ks2 + 4u;
    TFR(13) TFR(15) TFR(26) TFR(6)   x0 += ks2; x1 += k0  + 5u;
#undef TFR
    o0 = x0; o1 = x1;
}

__device__ __forceinline__ uint32_t jax_bits_p(uint32_t k0, uint32_t k1, uint32_t i)
{
    uint32_t o0, o1;
    tf2x32(k0, k1, 0u, i, o0, o1);
    return o0 ^ o1;
}

__device__ __forceinline__ float gumbel_from_bits(uint32_t bits)
{
    uint32_t fb = (bits >> 9) | 0x3f800000u;
    float f = __uint_as_float(fb) - 1.0f;
    const float TINY = 1.17549435e-38f;
    float u = (f > 0.0f) ? f : TINY;
    return -logf(-logf(u));
}

// ---------------- conversion kernels ----------------
__device__ __forceinline__ void split4h(float4 f, uint2& hi, uint2& lo)
{
    __half2 h0 = __floats2half2_rn(f.x, f.y);
    __half2 h1 = __floats2half2_rn(f.z, f.w);
    float r0 = f.x - __half2float(__low2half(h0));
    float r1 = f.y - __half2float(__high2half(h0));
    float r2 = f.z - __half2float(__low2half(h1));
    float r3 = f.w - __half2float(__high2half(h1));
    __half2 l0 = __floats2half2_rn(r0, r1);
    __half2 l1 = __floats2half2_rn(r2, r3);
    hi = make_uint2(*(uint32_t*)&h0, *(uint32_t*)&h1);
    lo = make_uint2(*(uint32_t*)&l0, *(uint32_t*)&l1);
}

__device__ __forceinline__ uint2 pack4h(float4 f)
{
    __half2 h0 = __floats2half2_rn(f.x, f.y);
    __half2 h1 = __floats2half2_rn(f.z, f.w);
    return make_uint2(*(uint32_t*)&h0, *(uint32_t*)&h1);
}

__global__ void cvt_a16(const float4* __restrict__ src, uint2* __restrict__ hi,
                        uint2* __restrict__ lo, int n4)
{
    int i = blockIdx.x*blockDim.x + threadIdx.x;
    if (i >= n4) return;
    uint2 h, l;
    split4h(src[i], h, l);
    hi[i] = h; lo[i] = l;
}

__global__ void cvt_w16(const float4* __restrict__ src, uint2* __restrict__ dst, int n4)
{
    int i = blockIdx.x*blockDim.x + threadIdx.x;
    if (i >= n4) return;
    dst[i] = pack4h(src[i]);
}

__global__ void cvt_pair16(const float4* __restrict__ s1, const float4* __restrict__ s2,
                           uint2* __restrict__ dst, int n4per)
{
    int e = blockIdx.z;
    int i = blockIdx.x*blockDim.x + threadIdx.x;
    if (i >= n4per) return;
    dst[(long long)(2*e)*n4per + i]   = pack4h(s1[(long long)e*n4per + i]);
    dst[(long long)(2*e+1)*n4per + i] = pack4h(s2[(long long)e*n4per + i]);
}

__global__ void silumul_pair16(const float4* __restrict__ H, uint2* __restrict__ hi,
                               uint2* __restrict__ lo, int total)
{
    int i = blockIdx.x*blockDim.x + threadIdx.x;
    if (i >= total) return;
    int row = i / 192, j = i % 192;
    float4 a = H[(long long)row*384 + j];
    float4 c = H[(long long)row*384 + 192 + j];
    float4 r;
    r.x = a.x/(1.f+expf(-a.x))*c.x;
    r.y = a.y/(1.f+expf(-a.y))*c.y;
    r.z = a.z/(1.f+expf(-a.z))*c.z;
    r.w = a.w/(1.f+expf(-a.w))*c.w;
    uint2 h, l;
    split4h(r, h, l);
    hi[i] = h; lo[i] = l;
}

__global__ void permute_x(const uint4* __restrict__ xh, const uint4* __restrict__ xl,
                          uint4* __restrict__ gh, uint4* __restrict__ gl)
{
    const int W16 = DM*2/16;  // 144
    int p = blockIdx.x;
    int src = g_idx[p];
    for (int c = threadIdx.x; c < W16; c += blockDim.x) {
        gh[(long long)p*W16 + c] = xh[(long long)src*W16 + c];
        gl[(long long)p*W16 + c] = xl[(long long)src*W16 + c];
    }
}

// ------------- shared GEMM building blocks (fp16-split 2-term) --------------
#define RSTR 144
#define AHS  0
#define ALS  18432
#define BS   36864
#define STG  55296
#define GSM_SIZE (2*STG + 512)

// ---------------- 512-thread GEMM (16 warps 4m x 4n, frag double-buffer) ----
template<int AMODE, int CMODE, int EPI>
__global__ __launch_bounds__(512, 1)
void gemm_cp(const __half* __restrict__ Ah, const __half* __restrict__ Al,
             int lda, long long aOff,
             const __half* __restrict__ W, int ldw, long long wOff,
             const float* __restrict__ bias,
             float* __restrict__ C, int ldc, long long cOff,
             const int* __restrict__ rowIdx, const int* __restrict__ bOffA,
             const int* __restrict__ bCnt, int bBase,
             const float* __restrict__ rowScale,
             __half* __restrict__ Yh, __half* __restrict__ Yl,
             int M, int N, int K)
{
    extern __shared__ char smc[];
    const uint32_t smb = smem_to_u32(smc);
    int* rmap = (int*)(smc + 2*STG);

    const int e = blockIdx.z;
    Ah += (long long)e * aOff; Al += (long long)e * aOff;
    W  += (long long)e * wOff;
    C  += (long long)e * cOff;

    int rows = M, aBase = 0;
    if (AMODE == 2) { rows = bCnt[bBase+e]; aBase = bOffA[bBase+e]; }
    const int m0 = blockIdx.y * 128, n0 = blockIdx.x * 128;
    if (m0 >= rows) return;

    const int tid = threadIdx.x, warp = tid >> 5, lane = tid & 31;
    const int wm = warp & 3, wn = warp >> 2;

    if (CMODE == 1 && tid < 128) {
        int r = m0 + tid;
        rmap[tid] = (r < rows) ? rowIdx[aBase + r] : -1;
    }
    if (CMODE == 1) __syncthreads();

    const int lrow = tid >> 2;
    const int seg  = tid & 3;
    const bool av = (m0 + lrow) < rows;
    const long long arow = (long long)(aBase + m0 + lrow);
    const __half* aSrcH = Ah + (av ? arow * lda : 0) + seg*8;
    const __half* aSrcL = Al + (av ? arow * lda : 0) + seg*8;
    const bool nok = (n0 + lrow) < N;
    const __half* bSrc = W + (nok ? (long long)(n0 + lrow) * ldw : 0) + seg*8;
    const uint32_t dRow = (uint32_t)lrow*RSTR + seg*16;
    const int kOff0 = seg*8, kOff1 = 32 + seg*8;

#define LOADS(c) { \
    const int k0 = (c)*64; \
    const uint32_t sb = smb + ((c)&1)*STG; \
    uint32_t a0 = (av  && (k0 + kOff0) < K) ? 16u : 0u; \
    uint32_t a1 = (av  && (k0 + kOff1) < K) ? 16u : 0u; \
    uint32_t b0 = (nok && (k0 + kOff0) < K) ? 16u : 0u; \
    uint32_t b1 = (nok && (k0 + kOff1) < K) ? 16u : 0u; \
    CPA(sb + AHS + dRow,      aSrcH + k0,      a0); \
    CPA(sb + AHS + dRow + 64, aSrcH + k0 + 32, a1); \
    CPA(sb + ALS + dRow,      aSrcL + k0,      a0); \
    CPA(sb + ALS + dRow + 64, aSrcL + k0 + 32, a1); \
    CPA(sb + BS  + dRow,      bSrc  + k0,      b0); \
    CPA(sb + BS  + dRow + 64, bSrc  + k0 + 32, b1); \
    CPA_COMMIT(); }

    const uint32_t aoff = (uint32_t)(lane & 15)*RSTR + (((uint32_t)lane >> 4) << 4);
    const uint32_t boff = (uint32_t)((lane & 7) + ((lane >> 4) << 3))*RSTR + (uint32_t)(((lane >> 3) & 1) << 4);

    float d[2][4][4];
    #pragma unroll
    for (int i = 0; i < 2; i++)
        #pragma unroll
        for (int j = 0; j < 4; j++)
            #pragma unroll
            for (int r = 0; r < 4; r++) d[i][j][r] = 0.f;

    uint32_t ahf[2][2][4], alf[2][2][4], bhf[2][2][4];

#define LDFRAG(fb, sb, ks) { \
    _Pragma("unroll") \
    for (int mt = 0; mt < 2; mt++) { \
        uint32_t ad = (sb) + (uint32_t)(wm*32 + mt*16)*RSTR + (ks)*32 + aoff; \
        LDSM4(ahf[fb][mt][0], ahf[fb][mt][1], ahf[fb][mt][2], ahf[fb][mt][3], ad); \
        LDSM4(alf[fb][mt][0], alf[fb][mt][1], alf[fb][mt][2], alf[fb][mt][3], ad + ALS); \
    } \
    _Pragma("unroll") \
    for (int ng = 0; ng < 2; ng++) { \
        uint32_t bd = (sb) + BS + (uint32_t)(wn*32 + ng*16)*RSTR + (ks)*32 + boff; \
        LDSM4(bhf[fb][ng][0], bhf[fb][ng][1], bhf[fb][ng][2], bhf[fb][ng][3], bd); \
    } }

#define DOMMA(fb) { \
    _Pragma("unroll") \
    for (int mt = 0; mt < 2; mt++) \
        _Pragma("unroll") \
        for (int ng = 0; ng < 2; ng++) \
            _Pragma("unroll") \
            for (int h = 0; h < 2; h++) \
                mma16f(d[mt][ng*2 + h], ahf[fb][mt], &bhf[fb][ng][2*h]); \
    _Pragma("unroll") \
    for (int mt = 0; mt < 2; mt++) \
        _Pragma("unroll") \
        for (int ng = 0; ng < 2; ng++) \
            _Pragma("unroll") \
            for (int h = 0; h < 2; h++) \
                mma16f(d[mt][ng*2 + h], alf[fb][mt], &bhf[fb][ng][2*h]); \
    }

    const int nc = (K + 63) / 64;
    LOADS(0)
    CPA_WAIT0();
    __syncthreads();
    LDFRAG(0, smb, 0)
    for (int c = 0; c < nc; c++) {
        const uint32_t sb = smb + (c & 1)*STG;
        if (c + 1 < nc) LOADS(c+1)
        #pragma unroll
        for (int ks = 0; ks < 4; ks++) {
            if (ks < 3) LDFRAG((ks+1)&1, sb, ks+1)
            DOMMA(ks&1)
        }
        if (c + 1 < nc) {
            CPA_WAIT0();
            __syncthreads();
            LDFRAG(0, smb + ((c+1)&1)*STG, 0)
        }
    }
#undef LOADS
#undef LDFRAG
#undef DOMMA

    #pragma unroll
    for (int mt = 0; mt < 2; mt++) {
        #pragma unroll
        for (int h = 0; h < 2; h++) {
            int r = wm*32 + mt*16 + (lane >> 2) + 8*h;
            if (m0 + r >= rows) continue;
            int cr = (CMODE == 0) ? (aBase + m0 + r) : rmap[r];
            if (cr < 0) continue;
            float* crow = C + (long long)cr * ldc;
            float sc = (EPI >= 1) ? rowScale[cr] : 0.f;
            #pragma unroll
            for (int n8 = 0; n8 < 4; n8++) {
                int c0 = n0 + wn*32 + n8*8 + (lane & 3)*2;
                if (c0 >= N) continue;
                float v0 = d[mt][n8][2*h + 0];
                float v1 = d[mt][n8][2*h + 1];
                if (EPI == 0) {
                    if (bias) { v0 += bias[c0]; v1 += bias[c0+1]; }
                    *(float2*)(crow + c0) = make_float2(v0, v1);
                } else if (EPI == 1) {
                    *(float2*)(crow + c0) = make_float2(v0*sc, v1*sc);
                } else {
                    float2 o = *(float2*)(crow + c0);
                    float f0 = o.x + v0*sc, f1 = o.y + v1*sc;
                    *(float2*)(crow + c0) = make_float2(f0, f1);
                    if (EPI == 3) {
                        __half2 hh = __floats2half2_rn(f0, f1);
                        float r0 = f0 - __half2float(__low2half(hh));
                        float r1 = f1 - __half2float(__high2half(hh));
                        __half2 ll = __floats2half2_rn(r0, r1);
                        *(__half2*)(Yh + (long long)cr*ldc + c0) = hh;
                        *(__half2*)(Yl + (long long)cr*ldc + c0) = ll;
                    }
                }
            }
        }
    }
}

// ---------------- 256-thread GEMM (8 warps 4m x 2n, 2 CTAs/SM) --------------
template<int AMODE, int CMODE, int EPI>
__global__ __launch_bounds__(256, 2)
void gemm_w2(const __half* __restrict__ Ah, const __half* __restrict__ Al,
             int lda, long long aOff,
             const __half* __restrict__ W, int ldw, long long wOff,
             const float* __restrict__ bias,
             float* __restrict__ C, int ldc, long long cOff,
             const int* __restrict__ rowIdx, const int* __restrict__ bOffA,
             const int* __restrict__ bCnt, int bBase,
             const float* __restrict__ rowScale,
             __half* __restrict__ Yh, __half* __restrict__ Yl,
             int M, int N, int K)
{
    extern __shared__ char smc[];
    const uint32_t smb = smem_to_u32(smc);
    int* rmap = (int*)(smc + 2*STG);

    const int e = blockIdx.z;
    Ah += (long long)e * aOff; Al += (long long)e * aOff;
    W  += (long long)e * wOff;
    C  += (long long)e * cOff;

    int rows = M, aBase = 0;
    if (AMODE == 2) { rows = bCnt[bBase+e]; aBase = bOffA[bBase+e]; }
    const int m0 = blockIdx.y * 128, n0 = blockIdx.x * 128;
    if (m0 >= rows) return;

    const int tid = threadIdx.x, warp = tid >> 5, lane = tid & 31;
    const int wm = warp & 3, wn = warp >> 2;   // 4m x 2n, warp tile 32x64

    if (CMODE == 1 && tid < 128) {
        int r = m0 + tid;
        rmap[tid] = (r < rows) ? rowIdx[aBase + r] : -1;
    }
    if (CMODE == 1) __syncthreads();

    // loaders: thread owns row tid>>1 (128 rows), 64B half (tid&1)
    const int lrow = tid >> 1;
    const int seg  = tid & 1;
    const bool av = (m0 + lrow) < rows;
    const long long arow = (long long)(aBase + m0 + lrow);
    const __half* aSrcH = Ah + (av ? arow * lda : 0) + seg*32;
    const __half* aSrcL = Al + (av ? arow * lda : 0) + seg*32;
    const bool nok = (n0 + lrow) < N;
    const __half* bSrc = W + (nok ? (long long)(n0 + lrow) * ldw : 0) + seg*32;
    const uint32_t dRow = (uint32_t)lrow*RSTR + seg*64;

#define LOADS(c) { \
    const int k0 = (c)*64; \
    const uint32_t sb = smb + ((c)&1)*STG; \
    _Pragma("unroll") \
    for (int j = 0; j < 4; j++) { \
        int kk = k0 + seg*32 + j*8; \
        uint32_t as = (av  && kk < K) ? 16u : 0u; \
        uint32_t bs = (nok && kk < K) ? 16u : 0u; \
        CPA(sb + AHS + dRow + j*16, aSrcH + k0 + j*8, as); \
        CPA(sb + ALS + dRow + j*16, aSrcL + k0 + j*8, as); \
        CPA(sb + BS  + dRow + j*16, bSrc  + k0 + j*8, bs); \
    } \
    CPA_COMMIT(); }

    const uint32_t aoff = (uint32_t)(lane & 15)*RSTR + (((uint32_t)lane >> 4) << 4);
    const uint32_t boff = (uint32_t)((lane & 7) + ((lane >> 4) << 3))*RSTR + (uint32_t)(((lane >> 3) & 1) << 4);

    float d[2][8][4];
    #pragma unroll
    for (int i = 0; i < 2; i++)
        #pragma unroll
        for (int j = 0; j < 8; j++)
            #pragma unroll
            for (int r = 0; r < 4; r++) d[i][j][r] = 0.f;

#define COMPUTES(buf) { \
    const uint32_t sb = smb + (buf)*STG; \
    _Pragma("unroll") \
    for (int ks = 0; ks < 4; ks++) { \
        uint32_t ah[2][4], al[2][4], bh[4][4]; \
        _Pragma("unroll") \
        for (int mt = 0; mt < 2; mt++) { \
            uint32_t ad = sb + (uint32_t)(wm*32 + mt*16)*RSTR + ks*32 + aoff; \
            LDSM4(ah[mt][0], ah[mt][1], ah[mt][2], ah[mt][3], ad); \
            LDSM4(al[mt][0], al[mt][1], al[mt][2], al[mt][3], ad + ALS); \
        } \
        _Pragma("unroll") \
        for (int ng = 0; ng < 4; ng++) { \
            uint32_t bd = sb + BS + (uint32_t)(wn*64 + ng*16)*RSTR + ks*32 + boff; \
            LDSM4(bh[ng][0], bh[ng][1], bh[ng][2], bh[ng][3], bd); \
        } \
        _Pragma("unroll") \
        for (int mt = 0; mt < 2; mt++) \
            _Pragma("unroll") \
            for (int ng = 0; ng < 4; ng++) \
                _Pragma("unroll") \
                for (int h = 0; h < 2; h++) \
                    mma16f(d[mt][ng*2 + h], ah[mt], &bh[ng][2*h]); \
        _Pragma("unroll") \
        for (int mt = 0; mt < 2; mt++) \
            _Pragma("unroll") \
            for (int ng = 0; ng < 4; ng++) \
                _Pragma("unroll") \
                for (int h = 0; h < 2; h++) \
                    mma16f(d[mt][ng*2 + h], al[mt], &bh[ng][2*h]); \
    } }

    const int nc = (K + 63) / 64;
    LOADS(0)
    for (int c = 0; c < nc; c++) {
        CPA_WAIT0();
        __syncthreads();
        if (c + 1 < nc) LOADS(c+1)
        COMPUTES(c & 1)
    }
#undef LOADS
#undef COMPUTES

    #pragma unroll
    for (int mt = 0; mt < 2; mt++) {
        #pragma unroll
        for (int h = 0; h < 2; h++) {
            int r = wm*32 + mt*16 + (lane >> 2) + 8*h;
            if (m0 + r >= rows) continue;
            int cr = (CMODE == 0) ? (aBase + m0 + r) : rmap[r];
            if (cr < 0) continue;
            float* crow = C + (long long)cr * ldc;
            float sc = (EPI >= 1) ? rowScale[cr] : 0.f;
            #pragma unroll
            for (int n8 = 0; n8 < 8; n8++) {
                int c0 = n0 + wn*64 + n8*8 + (lane & 3)*2;
                if (c0 >= N) continue;
                float v0 = d[mt][n8][2*h + 0];
                float v1 = d[mt][n8][2*h + 1];
                if (EPI == 0) {
                    if (bias) { v0 += bias[c0]; v1 += bias[c0+1]; }
                    *(float2*)(crow + c0) = make_float2(v0, v1);
                } else if (EPI == 1) {
                    *(float2*)(crow + c0) = make_float2(v0*sc, v1*sc);
                } else {
                    float2 o = *(float2*)(crow + c0);
                    float f0 = o.x + v0*sc, f1 = o.y + v1*sc;
                    *(float2*)(crow + c0) = make_float2(f0, f1);
                    if (EPI == 3) {
                        __half2 hh = __floats2half2_rn(f0, f1);
                        float r0 = f0 - __half2float(__low2half(hh));
                        float r1 = f1 - __half2float(__high2half(hh));
                        __half2 ll = __floats2half2_rn(r0, r1);
                        *(__half2*)(Yh + (long long)cr*ldc + c0) = hh;
                        *(__half2*)(Yl + (long long)cr*ldc + c0) = ll;
                    }
                }
            }
        }
    }
}

// ---------------- attention: 64 queries x (head,batch) per block ------------
// K/V read from combined KV buffer (ld = KVLD; V at +DM)
#define SMEM_ATTN 220160

__global__ __launch_bounds__(256)
void attn2(const float* __restrict__ Q, const float* __restrict__ KV,
           __half* __restrict__ Oh, __half* __restrict__ Ol)
{
    extern __shared__ float smatt[];
    float* Qs = smatt;
    float* Ks = smatt + 144*64;
    float* Vs = smatt + 144*64 + 144*128;
    float* Ss = Vs + 128*148;

    const int tid = threadIdx.x;
    const int q0 = blockIdx.x * 64;
    const int h = blockIdx.y, b = blockIdx.z;
    const long long qrow0 = (long long)b*1024 + q0;
    const int hc = h*144;

    for (int i = tid; i < 64*36; i += 256) {
        int q = i / 36, f = i % 36;
        float4 v4 = *(const float4*)(Q + (qrow0 + q)*DM + hc + f*4);
        Qs[(f*4+0)*64+q]=v4.x; Qs[(f*4+1)*64+q]=v4.y;
        Qs[(f*4+2)*64+q]=v4.z; Qs[(f*4+3)*64+q]=v4.w;
    }
    for (int i = tid; i < 128*36; i += 256) {
        int k = i / 36, f = i % 36;
        const float* kvrow = KV + (long long)(b*128 + k) * KVLD + hc;
        float4 v4 = *(const float4*)(kvrow + f*4);
        Ks[(f*4+0)*128+k]=v4.x; Ks[(f*4+1)*128+k]=v4.y;
        Ks[(f*4+2)*128+k]=v4.z; Ks[(f*4+3)*128+k]=v4.w;
        float4 w4 = *(const float4*)(kvrow + DM + f*4);
        *(float4*)&Vs[k*148 + f*4] = w4;
    }
    __syncthreads();

    const int tx = tid & 15, ty = tid >> 4;

    {
        float acc[4][8] = {};
        for (int d = 0; d < 144; d++) {
            float a[4], bv[8];
            *(float4*)a      = *(const float4*)&Qs[d*64 + ty*4];
            *(float4*)bv     = *(const float4*)&Ks[d*128 + tx*8];
            *(float4*)(bv+4) = *(const float4*)&Ks[d*128 + tx*8 + 4];
            #pragma unroll
            for (int i = 0; i < 4; i++)
                #pragma unroll
                for (int j = 0; j < 8; j++) acc[i][j] += a[i]*bv[j];
        }
        #pragma unroll
        for (int i = 0; i < 4; i++)
            #pragma unroll
            for (int j = 0; j < 8; j++)
                Ss[(ty*4+i)*132 + tx*8 + j] = acc[i][j] * (1.0f/12.0f);
    }
    __syncthreads();

    if (tid < 64) {
        float* r = Ss + tid*132;
        float mx = -1e30f;
        for (int k = 0; k < 128; k++) mx = fmaxf(mx, r[k]);
        float sum = 0.f;
        for (int k = 0; k < 128; k++) { float ev = expf(r[k]-mx); r[k] = ev; sum += ev; }
        float inv = 1.0f / sum;
        for (int k = 0; k < 128; k++) r[k] *= inv;
    }
    __syncthreads();

    {
        float o[4][9] = {};
        for (int k = 0; k < 128; k++) {
            float s[4];
            #pragma unroll
            for (int i = 0; i < 4; i++) s[i] = Ss[(ty*4+i)*132 + k];
            #pragma unroll
            for (int j = 0; j < 9; j++) {
                float vv = Vs[k*148 + tx*9 + j];
                #pragma unroll
                for (int i = 0; i < 4; i++) o[i][j] += s[i]*vv;
            }
        }
        #pragma unroll
        for (int i = 0; i < 4; i++)
            #pragma unroll
            for (int j = 0; j < 9; j++) {
                float v = o[i][j];
                __half hh = __float2half_rn(v);
                __half ll = __float2half_rn(v - __half2float(hh));
                long long off = (qrow0 + ty*4 + i)*DM + hc + tx*9 + j;
                Oh[off] = hh;
                Ol[off] = ll;
            }
    }
}

// ---------------- small exact kernels ----------------
__global__ void gate4(const float* __restrict__ A, const float* __restrict__ W,
                      const float* __restrict__ b, float* __restrict__ out)
{
    int w = blockIdx.x*8 + (threadIdx.x >> 5);
    int lane = threadIdx.x & 31;
    if (w >= NROW) return;
    const float* a = A + (long long)w*DM;
    float s0=0,s1=0,s2=0,s3=0;
    for (int c = lane*4; c < DM; c += 128) {
        float4 av = *(const float4*)(a + c);
        float4 w0 = *(const float4*)(W + c);
        float4 w1 = *(const float4*)(W + DM + c);
        float4 w2 = *(const float4*)(W + 2*DM + c);
        float4 w3 = *(const float4*)(W + 3*DM + c);
        s0 += av.x*w0.x + av.y*w0.y + av.z*w0.z + av.w*w0.w;
        s1 += av.x*w1.x + av.y*w1.y + av.z*w1.z + av.w*w1.w;
        s2 += av.x*w2.x + av.y*w2.y + av.z*w2.z + av.w*w2.w;
        s3 += av.x*w3.x + av.y*w3.y + av.z*w3.z + av.w*w3.w;
    }
    #pragma unroll
    for (int o = 16; o > 0; o >>= 1) {
        s0 += __shfl_xor_sync(0xffffffffu, s0, o);
        s1 += __shfl_xor_sync(0xffffffffu, s1, o);
        s2 += __shfl_xor_sync(0xffffffffu, s2, o);
        s3 += __shfl_xor_sync(0xffffffffu, s3, o);
    }
    if (lane == 0) {
        out[w*4+0] = s0 + b[0]; out[w*4+1] = s1 + b[1];
        out[w*4+2] = s2 + b[2]; out[w*4+3] = s3 + b[3];
    }
}

__global__ void hlk(const float* __restrict__ t, const float* __restrict__ w,
                    const float* __restrict__ bb, float* __restrict__ hl)
{
    int wi = threadIdx.x >> 5, lane = threadIdx.x & 31;
    int r = wi >> 1, o = wi & 1;
    const float* a = t + r*DM;
    const float* ww = w + o*DM;
    float s = 0.f;
    for (int c = lane*4; c < DM; c += 128) {
        float4 av = *(const float4*)(a + c);
        float4 wv = *(const float4*)(ww + c);
        s += av.x*wv.x + av.y*wv.y + av.z*wv.z + av.w*wv.w;
    }
    #pragma unroll
    for (int off = 16; off > 0; off >>= 1) s += __shfl_xor_sync(0xffffffffu, s, off);
    if (lane == 0) hl[r*2+o] = s + bb[o];
}

// ---------------- routing: gating + counts + offsets + scatter, one block ---
__global__ void route_all(const float* __restrict__ caplog, const float* __restrict__ aclog)
{
    __shared__ int scnt[8], scur[8];
    const int t = threadIdx.x;   // 1024 threads
    if (t < 8) scnt[t] = 0;
    __syncthreads();

    uint32_t k1a,k1b,k2a,k2b,k3a,k3b;
    tf2x32(0u, 42u, 0u, 0u, k1a, k1b);
    tf2x32(0u, 42u, 0u, 1u, k2a, k2b);
    tf2x32(0u, 42u, 0u, 2u, k3a, k3b);

    for (int n = t; n < NROW; n += 1024) {
        float g0 = gumbel_from_bits(jax_bits_p(k1a, k1b, 2u*(uint32_t)n + 0u));
        float g1 = gumbel_from_bits(jax_bits_p(k1a, k1b, 2u*(uint32_t)n + 1u));
        int bb = n >> 10;
        float l0 = g_hl[2*bb + 0] + g0;
        float l1 = g_hl[2*bb + 1] + g1;
        float mx = fmaxf(l0, l1);
        float e0 = expf(l0 - mx), e1 = expf(l1 - mx);
        float inv = 1.0f / (e0 + e1);
        g_cm[n] = e0 * inv;
        g_am[n] = e1 * inv;

        int be = 0; float bv = -1e30f;
        #pragma unroll
        for (int c = 0; c < 4; c++) {
            float g = gumbel_from_bits(jax_bits_p(k2a, k2b, 4u*(uint32_t)n + (uint32_t)c));
            float yv = caplog[n*4 + c] + g;
            if (yv > bv) { bv = yv; be = c; }
        }
        g_cpe[n] = be;
        atomicAdd(&scnt[be], 1);

        int ae = 0; bv = -1e30f;
        #pragma unroll
        for (int c = 0; c < 4; c++) {
            float g = gumbel_from_bits(jax_bits_p(k3a, k3b, 4u*(uint32_t)n + (uint32_t)c));
            float yv = aclog[n*4 + c] + g;
            if (yv > bv) { bv = yv; ae = c; }
        }
        g_ape[n] = ae;
        atomicAdd(&scnt[4 + ae], 1);
    }
    __syncthreads();

    if (t == 0) {
        int o = 0;
        for (int e2 = 0; e2 < 4; e2++) { g_off[e2] = o; scur[e2] = o; g_cnt[e2] = scnt[e2]; o += scnt[e2]; }
        o = NROW;
        for (int e2 = 4; e2 < 8; e2++) { g_off[e2] = o; scur[e2] = o; g_cnt[e2] = scnt[e2]; o += scnt[e2]; }
    }
    __syncthreads();

    for (int n = t; n < NROW; n += 1024) {
        int p = atomicAdd(&scur[g_cpe[n]], 1);
        g_idx[p] = n;
        p = atomicAdd(&scur[4 + g_ape[n]], 1);
        g_idx[p] = n;
    }
}

// ---------------- lb loss ----------------
__global__ void lb_kernel(float* __restrict__ outp, long long i1)
{
    __shared__ float sh[256 * 9];
    int t = threadIdx.x;
    float u[8] = {0,0,0,0,0,0,0,0};
    float ms = 0.f;
    for (int n = t; n < NROW; n += 256) {
        u[g_cpe[n]]     += g_cm[n];
        u[4 + g_ape[n]] += g_am[n];
        ms += g_cm[n] + g_am[n];
    }
    #pragma unroll
    for (int j = 0; j < 8; j++) sh[t*9 + j] = u[j];
    sh[t*9 + 8] = ms;
    __syncthreads();
    for (int stride = 128; stride > 0; stride >>= 1) {
        if (t < stride)
            #pragma unroll
            for (int j = 0; j < 9; j++) sh[t*9 + j] += sh[(t + stride)*9 + j];
        __syncthreads();
    }
    if (t == 0 && i1 >= 0) {
        float denom = 4.0f * sh[8] + 1e-10f;
        float acc = 0.f;
        for (int j = 0; j < 8; j++) {
            float uu = sh[j] / denom;
            acc += uu * logf(uu + 1e-10f);
        }
        outp[i1] = acc / 8.0f;
    }
}

// ---------------- host launcher ----------------
static inline void cvtA(const float* src, __half* h, __half* l, long long n)
{
    int n4 = (int)(n / 4);
    cvt_a16<<<(n4 + 255)/256, 256>>>((const float4*)src, (uint2*)h, (uint2*)l, n4);
}
static inline void cvtW(const float* src, __half* d, long long n)
{
    int n4 = (int)(n / 4);
    cvt_w16<<<(n4 + 255)/256, 256>>>((const float4*)src, (uint2*)d, n4);
}

extern "C" void kernel_launch(void* const* d_in, const int* in_sizes, int n_in,
                              void* d_out, int out_size)
{
    const float* x        = (const float*)d_in[0];
    const float* timei    = (const float*)d_in[1];
    const float* caption  = (const float*)d_in[2];
    const float* acoustic = (const float*)d_in[3];
    const float* w_in     = (const float*)d_in[4];
    const float* b_in     = (const float*)d_in[5];
    const float* w_out    = (const float*)d_in[6];
    const float* b_out    = (const float*)d_in[7];
    const float* hlw      = (const float*)d_in[8];
    const float* hlb      = (const float*)d_in[9];
    const float* cgw      = (const float*)d_in[10];
    const float* cgb      = (const float*)d_in[11];
    const float* agw      = (const float*)d_in[12];
    const float* agb      = (const float*)d_in[13];
    const float* cw1      = (const float*)d_in[14];
    const float* cw2      = (const float*)d_in[15];
    const float* cw3      = (const float*)d_in[16];
    const float* aw1      = (const float*)d_in[17];
    const float* aw2      = (const float*)d_in[18];
    const float* aw3      = (const float*)d_in[19];
    const float* fw1      = (const float*)d_in[20];
    const float* fw2      = (const float*)d_in[21];
    const float* fw3      = (const float*)d_in[22];
    float* out = (float*)d_out;

    float *pq,*pkv,*pcap2,*pclog,*palog,*phl,*pcm,*pam,*pH,*pR,*py;
    int *pidx,*poff,*pcnt;
    __half *xh,*xl,*gxh,*gxl,*cph,*cpl,*win16,*wout16,*ew16,*cah,*cal,*Hh,*Hl,*yh,*yl,*Rh,*Rl;

    cudaGetSymbolAddress((void**)&pq,    g_q);
    cudaGetSymbolAddress((void**)&pkv,   g_kv);
    cudaGetSymbolAddress((void**)&pcap2, g_cap2);
    cudaGetSymbolAddress((void**)&pclog, g_caplog);
    cudaGetSymbolAddress((void**)&palog, g_aclog);
    cudaGetSymbolAddress((void**)&phl,   g_hl);
    cudaGetSymbolAddress((void**)&pcm,   g_cm);
    cudaGetSymbolAddress((void**)&pam,   g_am);
    cudaGetSymbolAddress((void**)&pH,    g_H);
    cudaGetSymbolAddress((void**)&pR,    g_R);
    cudaGetSymbolAddress((void**)&py,    g_y);
    cudaGetSymbolAddress((void**)&pidx,  g_idx);
    cudaGetSymbolAddress((void**)&poff,  g_off);
    cudaGetSymbolAddress((void**)&pcnt,  g_cnt);
    cudaGetSymbolAddress((void**)&xh,    g_xh);
    cudaGetSymbolAddress((void**)&xl,    g_xl);
    cudaGetSymbolAddress((void**)&gxh,   g_gxh);
    cudaGetSymbolAddress((void**)&gxl,   g_gxl);
    cudaGetSymbolAddress((void**)&cph,   g_caph);
    cudaGetSymbolAddress((void**)&cpl,   g_capl);
    cudaGetSymbolAddress((void**)&win16, g_win16);
    cudaGetSymbolAddress((void**)&wout16,g_wout16);
    cudaGetSymbolAddress((void**)&ew16,  g_ew16);
    cudaGetSymbolAddress((void**)&cah,   g_cah);
    cudaGetSymbolAddress((void**)&cal,   g_cal);
    cudaGetSymbolAddress((void**)&Hh,    g_Hh);
    cudaGetSymbolAddress((void**)&Hl,    g_Hl);
    cudaGetSymbolAddress((void**)&yh,    g_yh);
    cudaGetSymbolAddress((void**)&yl,    g_yl);
    cudaGetSymbolAddress((void**)&Rh,    g_Rh);
    cudaGetSymbolAddress((void**)&Rl,    g_Rl);

    cudaFuncSetAttribute(attn2, cudaFuncAttributeMaxDynamicSharedMemorySize, SMEM_ATTN);
    cudaFuncSetAttribute(gemm_cp<0,0,0>, cudaFuncAttributeMaxDynamicSharedMemorySize, GSM_SIZE);
    cudaFuncSetAttribute(gemm_w2<2,0,0>, cudaFuncAttributeMaxDynamicSharedMemorySize, GSM_SIZE);
    cudaFuncSetAttribute(gemm_w2<2,1,1>, cudaFuncAttributeMaxDynamicSharedMemorySize, GSM_SIZE);
    cudaFuncSetAttribute(gemm_w2<2,1,3>, cudaFuncAttributeMaxDynamicSharedMemorySize, GSM_SIZE);
    cudaFuncSetAttribute(gemm_w2<0,0,0>, cudaFuncAttributeMaxDynamicSharedMemorySize, GSM_SIZE);

    const int n4per = HDM/4;

    cvtA(x, xh, xl, (long long)NROW*DM);
    cvtW(w_in, win16, 3LL*DM*DM);
    cvtA(caption, cph, cpl, (long long)SKV*DM);
    // Q (profiled slot #4)
    gemm_cp<0,0,0><<<dim3(9,16,1),512,GSM_SIZE>>>(xh, xl, DM, 0, win16, DM, 0, b_in,
        pq, DM, 0, nullptr,nullptr,nullptr,0, nullptr, nullptr, nullptr, NROW, DM, DM);
    // K|V merged (N = 2304)
    gemm_cp<0,0,0><<<dim3(18,2,1),512,GSM_SIZE>>>(cph, cpl, DM, 0, win16 + (long long)DM*DM, DM, 0, b_in + DM,
        pkv, KVLD, 0, nullptr,nullptr,nullptr,0, nullptr, nullptr, nullptr, SKV, KVLD, DM);
    cvtW(w_out, wout16, (long long)DM*DM);
    // attention -> fp16 hi/lo directly
    attn2<<<dim3(16,8,2),256,SMEM_ATTN>>>(pq, pkv, cah, cal);
    // out proj
    gemm_cp<0,0,0><<<dim3(9,16,1),512,GSM_SIZE>>>(cah, cal, DM, 0, wout16, DM, 0, b_out,
        pcap2, DM, 0, nullptr,nullptr,nullptr,0, nullptr, nullptr, nullptr, NROW, DM, DM);
    // hl + gate logits (exact fp32)
    hlk<<<1,128>>>(timei, hlw, hlb, phl);
    gate4<<<NROW/8,256>>>(pcap2, cgw, cgb, pclog);
    gate4<<<NROW/8,256>>>(acoustic, agw, agb, palog);
    // gating + routing (one block)
    route_all<<<1,1024>>>(pclog, palog);
    // expert weight conversions into slots
    dim3 pg((n4per + 255)/256, 1, 4);
    cvt_pair16<<<pg,256>>>((const float4*)cw1, (const float4*)cw3, (uint2*)(ew16 + 0LL*HDM),  n4per);
    cvt_pair16<<<pg,256>>>((const float4*)aw1, (const float4*)aw3, (uint2*)(ew16 + 8LL*HDM),  n4per);
    cvtW(cw2, ew16 + 16LL*HDM, 4LL*HDM);
    cvtW(aw2, ew16 + 20LL*HDM, 4LL*HDM);
    cvt_pair16<<<pg,256>>>((const float4*)fw1, (const float4*)fw3, (uint2*)(ew16 + 24LL*HDM), n4per);
    cvtW(fw2, ew16 + 32LL*HDM, 4LL*HDM);
    // permute x rows into bucket order
    permute_x<<<2*NROW,128>>>((const uint4*)xh, (const uint4*)xl, (uint4*)gxh, (uint4*)gxl);
    // MoE up: one GEMM, z=8 buckets, N=1536 (2-CTA variant)
    gemm_w2<2,0,0><<<dim3(12,16,8),256,GSM_SIZE>>>(gxh, gxl, DM, 0,
        ew16, DM, 2LL*HDM, nullptr,
        pH, 1536, 0, nullptr, poff, pcnt, 0, nullptr, nullptr, nullptr, NROW, 1536, DM);
    silumul_pair16<<<(4096*192 + 255)/256,256>>>((const float4*)pH, (uint2*)Hh, (uint2*)Hl, 4096*192);
    // MoE down cap / ac
    gemm_w2<2,1,1><<<dim3(9,16,4),256,GSM_SIZE>>>(Hh, Hl, HIDN, 0,
        ew16 + 16LL*HDM, HIDN, (long long)HDM, nullptr,
        py, DM, 0, pidx, poff, pcnt, 0, pcm, nullptr, nullptr, NROW, DM, HIDN);
    gemm_w2<2,1,3><<<dim3(9,16,4),256,GSM_SIZE>>>(Hh, Hl, HIDN, 0,
        ew16 + 20LL*HDM, HIDN, (long long)HDM, nullptr,
        py, DM, 0, pidx, poff, pcnt, 4, pam, yh, yl, NROW, DM, HIDN);
    // region FF
    gemm_w2<0,0,0><<<dim3(12,16,4),256,GSM_SIZE>>>(yh, yl, DM, REG,
        ew16 + 24LL*HDM, DM, 2LL*HDM + REG, nullptr,
        pR, 1536, 2048LL*1536, nullptr,nullptr,nullptr,0, nullptr, nullptr, nullptr, NROW, 1536, REG);
    silumul_pair16<<<(8192*192 + 255)/256,256>>>((const float4*)pR, (uint2*)Rh, (uint2*)Rl, 8192*192);
    gemm_w2<0,0,0><<<dim3(3,16,4),256,GSM_SIZE>>>(Rh, Rl, HIDN, 2048LL*HIDN,
        ew16 + 32LL*HDM, HIDN, (long long)HDM + (long long)REG*HIDN, nullptr,
        out, DM, REG, nullptr,nullptr,nullptr,0, nullptr, nullptr, nullptr, NROW, REG, HIDN);
    // lb loss scalar
    long long zElems = (long long)NROW * DM;
    long long i1 = ((long long)out_size > zElems) ? zElems : -1;
    lb_kernel<<<1,256>>>(out, i1);
}

// round 17
// speedup vs baseline: 1.0768x; 1.0768x over previous
#include <cuda_runtime.h>
#include <cuda_fp16.h>
#include <cstdint>

#define NROW 2048
#define DM   1152
#define SKV  256
#define HIDN 768
#define REG  288            // DM/4
#define HDM  (HIDN*DM)      // one expert matrix (either orientation)
#define KVLD 2304           // combined K|V row stride

// ---------------- scratch (device globals; allocation-free) ----------------
__device__ float g_q[NROW*DM];
__device__ float g_kv[SKV*KVLD];
__device__ float g_cap2[NROW*DM];
__device__ float g_caplog[NROW*4];
__device__ float g_aclog[NROW*4];
__device__ float g_hl[4];
__device__ float g_cm[NROW];
__device__ float g_am[NROW];
__device__ int   g_cpe[NROW];
__device__ int   g_ape[NROW];
__device__ int   g_cnt[8];
__device__ int   g_off[8];
__device__ int   g_idx[2*NROW];          // perm position -> original row
__device__ float g_H[4096L*1536];        // MoE up combined (h1|h3), perm order
__device__ float g_R[8192L*1536];        // region up combined
__device__ float g_y[NROW*DM];

// fp16 operands: activations hi/lo (A side), weights single fp16 (B side)
__device__ __half g_xh[NROW*DM],  g_xl[NROW*DM];
__device__ __half g_gxh[2*NROW*DM], g_gxl[2*NROW*DM];
__device__ __half g_caph[SKV*DM], g_capl[SKV*DM];
__device__ __half g_win16[3*DM*DM];
__device__ __half g_wout16[DM*DM];
__device__ __half g_ew16[36L*HDM];
__device__ __half g_cah[NROW*DM], g_cal[NROW*DM];
__device__ __half g_Hh[4096L*HIDN], g_Hl[4096L*HIDN];
__device__ __half g_yh[NROW*DM],  g_yl[NROW*DM];
__device__ __half g_Rh[8192L*HIDN], g_Rl[8192L*HIDN];

// ---------------- helpers ----------------
__device__ __forceinline__ uint32_t smem_to_u32(const void* p) {
    uint32_t a;
    asm("{ .reg .u64 t; cvta.to.shared.u64 t, %1; cvt.u32.u64 %0, t; }" : "=r"(a) : "l"(p));
    return a;
}

#define CPA(dst, src, sz) \
    asm volatile("cp.async.cg.shared.global [%0], [%1], 16, %2;" \
                 :: "r"(dst), "l"(src), "r"(sz) : "memory")
#define CPA_COMMIT() asm volatile("cp.async.commit_group;" ::: "memory")
#define CPA_WAIT0()  asm volatile("cp.async.wait_group 0;" ::: "memory")

#define LDSM4(r0, r1, r2, r3, addr) \
    asm volatile("ldmatrix.sync.aligned.m8n8.x4.shared.b16 {%0,%1,%2,%3}, [%4];" \
                 : "=r"(r0), "=r"(r1), "=r"(r2), "=r"(r3) : "r"(addr))

__device__ __forceinline__ void mma16f(float* d, const uint32_t* a, const uint32_t* b)
{
    asm volatile(
        "mma.sync.aligned.m16n8k16.row.col.f32.f16.f16.f32 "
        "{%0,%1,%2,%3}, {%4,%5,%6,%7}, {%8,%9}, {%0,%1,%2,%3};\n"
        : "+f"(d[0]), "+f"(d[1]), "+f"(d[2]), "+f"(d[3])
        : "r"(a[0]), "r"(a[1]), "r"(a[2]), "r"(a[3]), "r"(b[0]), "r"(b[1]));
}

// ---------------- threefry2x32-20 (exact JAX, partitionable) ----------------
__device__ __forceinline__ uint32_t rotl32(uint32_t v, int r){ return (v<<r)|(v>>(32-r)); }

__device__ __forceinline__ void tf2x32(uint32_t k0, uint32_t k1, uint32_t x0, uint32_t x1,
                                       uint32_t& o0, uint32_t& o1)
{
    uint32_t ks2 = k0 ^ k1 ^ 0x1BD11BDAu;
    x0 += k0; x1 += k1;
#define TFR(r) { x0 += x1; x1 = rotl32(x1,(r)); x1 ^= x0; }
    TFR(13) TFR(15) TFR(26) TFR(6)   x0 += k1;  x1 += ks2 + 1u;
    TFR(17) TFR(29) TFR(16) TFR(24)  x0 += ks2; x1 += k0  + 2u;
    TFR(13) TFR(15) TFR(26) TFR(6)   x0 += k0;  x1 += k1  + 3u;
    TFR(17) TFR(29) TFR(16) TFR(24)  x0 += k1;  x1 += ks2 + 4u;
    TFR(13) TFR(15) TFR(26) TFR(6)   x0 += ks2; x1 += k0  + 5u;
#undef TFR
    o0 = x0; o1 = x1;
}

__device__ __forceinline__ uint32_t jax_bits_p(uint32_t k0, uint32_t k1, uint32_t i)
{
    uint32_t o0, o1;
    tf2x32(k0, k1, 0u, i, o0, o1);
    return o0 ^ o1;
}

__device__ __forceinline__ float gumbel_from_bits(uint32_t bits)
{
    uint32_t fb = (bits >> 9) | 0x3f800000u;
    float f = __uint_as_float(fb) - 1.0f;
    const float TINY = 1.17549435e-38f;
    float u = (f > 0.0f) ? f : TINY;
    return -logf(-logf(u));
}

// ---------------- conversion kernels ----------------
__device__ __forceinline__ void split4h(float4 f, uint2& hi, uint2& lo)
{
    __half2 h0 = __floats2half2_rn(f.x, f.y);
    __half2 h1 = __floats2half2_rn(f.z, f.w);
    float r0 = f.x - __half2float(__low2half(h0));
    float r1 = f.y - __half2float(__high2half(h0));
    float r2 = f.z - __half2float(__low2half(h1));
    float r3 = f.w - __half2float(__high2half(h1));
    __half2 l0 = __floats2half2_rn(r0, r1);
    __half2 l1 = __floats2half2_rn(r2, r3);
    hi = make_uint2(*(uint32_t*)&h0, *(uint32_t*)&h1);
    lo = make_uint2(*(uint32_t*)&l0, *(uint32_t*)&l1);
}

__device__ __forceinline__ uint2 pack4h(float4 f)
{
    __half2 h0 = __floats2half2_rn(f.x, f.y);
    __half2 h1 = __floats2half2_rn(f.z, f.w);
    return make_uint2(*(uint32_t*)&h0, *(uint32_t*)&h1);
}

__global__ void cvt_a16(const float4* __restrict__ src, uint2* __restrict__ hi,
                        uint2* __restrict__ lo, int n4)
{
    int i = blockIdx.x*blockDim.x + threadIdx.x;
    if (i >= n4) return;
    uint2 h, l;
    split4h(src[i], h, l);
    hi[i] = h; lo[i] = l;
}

__global__ void cvt_w16(const float4* __restrict__ src, uint2* __restrict__ dst, int n4)
{
    int i = blockIdx.x*blockDim.x + threadIdx.x;
    if (i >= n4) return;
    dst[i] = pack4h(src[i]);
}

__global__ void cvt_pair16(const float4* __restrict__ s1, const float4* __restrict__ s2,
                           uint2* __restrict__ dst, int n4per)
{
    int e = blockIdx.z;
    int i = blockIdx.x*blockDim.x + threadIdx.x;
    if (i >= n4per) return;
    dst[(long long)(2*e)*n4per + i]   = pack4h(s1[(long long)e*n4per + i]);
    dst[(long long)(2*e+1)*n4per + i] = pack4h(s2[(long long)e*n4per + i]);
}

__global__ void silumul_pair16(const float4* __restrict__ H, uint2* __restrict__ hi,
                               uint2* __restrict__ lo, int total)
{
    int i = blockIdx.x*blockDim.x + threadIdx.x;
    if (i >= total) return;
    int row = i / 192, j = i % 192;
    float4 a = H[(long long)row*384 + j];
    float4 c = H[(long long)row*384 + 192 + j];
    float4 r;
    r.x = a.x/(1.f+expf(-a.x))*c.x;
    r.y = a.y/(1.f+expf(-a.y))*c.y;
    r.z = a.z/(1.f+expf(-a.z))*c.z;
    r.w = a.w/(1.f+expf(-a.w))*c.w;
    uint2 h, l;
    split4h(r, h, l);
    hi[i] = h; lo[i] = l;
}

__global__ void permute_x(const uint4* __restrict__ xh, const uint4* __restrict__ xl,
                          uint4* __restrict__ gh, uint4* __restrict__ gl)
{
    const int W16 = DM*2/16;  // 144
    int p = blockIdx.x;
    int src = g_idx[p];
    for (int c = threadIdx.x; c < W16; c += blockDim.x) {
        gh[(long long)p*W16 + c] = xh[(long long)src*W16 + c];
        gl[(long long)p*W16 + c] = xl[(long long)src*W16 + c];
    }
}

// ---------------- fp16-split warp-MMA GEMM (2-term, K-chunk 64, 2-stage) ----
// Tile 128(M) x 128(N) x 64(K); 512 threads, 16 warps (4m x 4n, warp 32x32).
// Fragment double-buffering hides LDSM latency behind MMAs. Per-accumulator
// MMA order fixed across rounds -> bit-identical results.
// EPI: 0 store(+bias), 1 store*rowScale, 2 +=*rowScale, 3 = EPI2 + emit fp16 hi/lo.
#define RSTR 144
#define AHS  0
#define ALS  18432
#define BS   36864
#define STG  55296
#define GSM_SIZE (2*STG + 512)

template<int AMODE, int CMODE, int EPI>
__global__ __launch_bounds__(512, 1)
void gemm_cp(const __half* __restrict__ Ah, const __half* __restrict__ Al,
             int lda, long long aOff,
             const __half* __restrict__ W, int ldw, long long wOff,
             const float* __restrict__ bias,
             float* __restrict__ C, int ldc, long long cOff,
             const int* __restrict__ rowIdx, const int* __restrict__ bOffA,
             const int* __restrict__ bCnt, int bBase,
             const float* __restrict__ rowScale,
             __half* __restrict__ Yh, __half* __restrict__ Yl,
             int M, int N, int K)
{
    extern __shared__ char smc[];
    const uint32_t smb = smem_to_u32(smc);
    int* rmap = (int*)(smc + 2*STG);

    const int e = blockIdx.z;
    Ah += (long long)e * aOff; Al += (long long)e * aOff;
    W  += (long long)e * wOff;
    C  += (long long)e * cOff;

    int rows = M, aBase = 0;
    if (AMODE == 2) { rows = bCnt[bBase+e]; aBase = bOffA[bBase+e]; }
    const int m0 = blockIdx.y * 128, n0 = blockIdx.x * 128;
    if (m0 >= rows) return;

    const int tid = threadIdx.x, warp = tid >> 5, lane = tid & 31;
    const int wm = warp & 3, wn = warp >> 2;

    if (CMODE == 1 && tid < 128) {
        int r = m0 + tid;
        rmap[tid] = (r < rows) ? rowIdx[aBase + r] : -1;
    }
    if (CMODE == 1) __syncthreads();

    const int lrow = tid >> 2;
    const int seg  = tid & 3;
    const bool av = (m0 + lrow) < rows;
    const long long arow = (long long)(aBase + m0 + lrow);
    const __half* aSrcH = Ah + (av ? arow * lda : 0) + seg*8;
    const __half* aSrcL = Al + (av ? arow * lda : 0) + seg*8;
    const bool nok = (n0 + lrow) < N;
    const __half* bSrc = W + (nok ? (long long)(n0 + lrow) * ldw : 0) + seg*8;
    const uint32_t dRow = (uint32_t)lrow*RSTR + seg*16;
    const int kOff0 = seg*8, kOff1 = 32 + seg*8;

#define LOADS(c) { \
    const int k0 = (c)*64; \
    const uint32_t sb = smb + ((c)&1)*STG; \
    uint32_t a0 = (av  && (k0 + kOff0) < K) ? 16u : 0u; \
    uint32_t a1 = (av  && (k0 + kOff1) < K) ? 16u : 0u; \
    uint32_t b0 = (nok && (k0 + kOff0) < K) ? 16u : 0u; \
    uint32_t b1 = (nok && (k0 + kOff1) < K) ? 16u : 0u; \
    CPA(sb + AHS + dRow,      aSrcH + k0,      a0); \
    CPA(sb + AHS + dRow + 64, aSrcH + k0 + 32, a1); \
    CPA(sb + ALS + dRow,      aSrcL + k0,      a0); \
    CPA(sb + ALS + dRow + 64, aSrcL + k0 + 32, a1); \
    CPA(sb + BS  + dRow,      bSrc  + k0,      b0); \
    CPA(sb + BS  + dRow + 64, bSrc  + k0 + 32, b1); \
    CPA_COMMIT(); }

    const uint32_t aoff = (uint32_t)(lane & 15)*RSTR + (((uint32_t)lane >> 4) << 4);
    const uint32_t boff = (uint32_t)((lane & 7) + ((lane >> 4) << 3))*RSTR + (uint32_t)(((lane >> 3) & 1) << 4);

    float d[2][4][4];
    #pragma unroll
    for (int i = 0; i < 2; i++)
        #pragma unroll
        for (int j = 0; j < 4; j++)
            #pragma unroll
            for (int r = 0; r < 4; r++) d[i][j][r] = 0.f;

    uint32_t ahf[2][2][4], alf[2][2][4], bhf[2][2][4];

#define LDFRAG(fb, sb, ks) { \
    _Pragma("unroll") \
    for (int mt = 0; mt < 2; mt++) { \
        uint32_t ad = (sb) + (uint32_t)(wm*32 + mt*16)*RSTR + (ks)*32 + aoff; \
        LDSM4(ahf[fb][mt][0], ahf[fb][mt][1], ahf[fb][mt][2], ahf[fb][mt][3], ad); \
        LDSM4(alf[fb][mt][0], alf[fb][mt][1], alf[fb][mt][2], alf[fb][mt][3], ad + ALS); \
    } \
    _Pragma("unroll") \
    for (int ng = 0; ng < 2; ng++) { \
        uint32_t bd = (sb) + BS + (uint32_t)(wn*32 + ng*16)*RSTR + (ks)*32 + boff; \
        LDSM4(bhf[fb][ng][0], bhf[fb][ng][1], bhf[fb][ng][2], bhf[fb][ng][3], bd); \
    } }

#define DOMMA(fb) { \
    _Pragma("unroll") \
    for (int mt = 0; mt < 2; mt++) \
        _Pragma("unroll") \
        for (int ng = 0; ng < 2; ng++) \
            _Pragma("unroll") \
            for (int h = 0; h < 2; h++) \
                mma16f(d[mt][ng*2 + h], ahf[fb][mt], &bhf[fb][ng][2*h]); \
    _Pragma("unroll") \
    for (int mt = 0; mt < 2; mt++) \
        _Pragma("unroll") \
        for (int ng = 0; ng < 2; ng++) \
            _Pragma("unroll") \
            for (int h = 0; h < 2; h++) \
                mma16f(d[mt][ng*2 + h], alf[fb][mt], &bhf[fb][ng][2*h]); \
    }

    const int nc = (K + 63) / 64;
    LOADS(0)
    CPA_WAIT0();
    __syncthreads();
    LDFRAG(0, smb, 0)
    for (int c = 0; c < nc; c++) {
        const uint32_t sb = smb + (c & 1)*STG;
        if (c + 1 < nc) LOADS(c+1)
        #pragma unroll
        for (int ks = 0; ks < 4; ks++) {
            if (ks < 3) LDFRAG((ks+1)&1, sb, ks+1)
            DOMMA(ks&1)
        }
        if (c + 1 < nc) {
            CPA_WAIT0();
            __syncthreads();
            LDFRAG(0, smb + ((c+1)&1)*STG, 0)
        }
    }
#undef LOADS
#undef LDFRAG
#undef DOMMA

    #pragma unroll
    for (int mt = 0; mt < 2; mt++) {
        #pragma unroll
        for (int h = 0; h < 2; h++) {
            int r = wm*32 + mt*16 + (lane >> 2) + 8*h;
            if (m0 + r >= rows) continue;
            int cr = (CMODE == 0) ? (aBase + m0 + r) : rmap[r];
            if (cr < 0) continue;
            float* crow = C + (long long)cr * ldc;
            float sc = (EPI >= 1) ? rowScale[cr] : 0.f;
            #pragma unroll
            for (int n8 = 0; n8 < 4; n8++) {
                int c0 = n0 + wn*32 + n8*8 + (lane & 3)*2;
                if (c0 >= N) continue;
                float v0 = d[mt][n8][2*h + 0];
                float v1 = d[mt][n8][2*h + 1];
                if (EPI == 0) {
                    if (bias) { v0 += bias[c0]; v1 += bias[c0+1]; }
                    *(float2*)(crow + c0) = make_float2(v0, v1);
                } else if (EPI == 1) {
                    *(float2*)(crow + c0) = make_float2(v0*sc, v1*sc);
                } else {
                    float2 o = *(float2*)(crow + c0);
                    float f0 = o.x + v0*sc, f1 = o.y + v1*sc;
                    *(float2*)(crow + c0) = make_float2(f0, f1);
                    if (EPI == 3) {
                        __half2 hh = __floats2half2_rn(f0, f1);
                        float r0 = f0 - __half2float(__low2half(hh));
                        float r1 = f1 - __half2float(__high2half(hh));
                        __half2 ll = __floats2half2_rn(r0, r1);
                        *(__half2*)(Yh + (long long)cr*ldc + c0) = hh;
                        *(__half2*)(Yl + (long long)cr*ldc + c0) = ll;
                    }
                }
            }
        }
    }
}

// ---------------- attention: 64 queries x (head,batch) per block ------------
// K/V read from combined KV buffer (ld = KVLD; V at +DM)
#define SMEM_ATTN 220160

__global__ __launch_bounds__(256)
void attn2(const float* __restrict__ Q, const float* __restrict__ KV,
           __half* __restrict__ Oh, __half* __restrict__ Ol)
{
    extern __shared__ float smatt[];
    float* Qs = smatt;
    float* Ks = smatt + 144*64;
    float* Vs = smatt + 144*64 + 144*128;
    float* Ss = Vs + 128*148;

    const int tid = threadIdx.x;
    const int q0 = blockIdx.x * 64;
    const int h = blockIdx.y, b = blockIdx.z;
    const long long qrow0 = (long long)b*1024 + q0;
    const int hc = h*144;

    for (int i = tid; i < 64*36; i += 256) {
        int q = i / 36, f = i % 36;
        float4 v4 = *(const float4*)(Q + (qrow0 + q)*DM + hc + f*4);
        Qs[(f*4+0)*64+q]=v4.x; Qs[(f*4+1)*64+q]=v4.y;
        Qs[(f*4+2)*64+q]=v4.z; Qs[(f*4+3)*64+q]=v4.w;
    }
    for (int i = tid; i < 128*36; i += 256) {
        int k = i / 36, f = i % 36;
        const float* kvrow = KV + (long long)(b*128 + k) * KVLD + hc;
        float4 v4 = *(const float4*)(kvrow + f*4);
        Ks[(f*4+0)*128+k]=v4.x; Ks[(f*4+1)*128+k]=v4.y;
        Ks[(f*4+2)*128+k]=v4.z; Ks[(f*4+3)*128+k]=v4.w;
        float4 w4 = *(const float4*)(kvrow + DM + f*4);
        *(float4*)&Vs[k*148 + f*4] = w4;
    }
    __syncthreads();

    const int tx = tid & 15, ty = tid >> 4;

    {
        float acc[4][8] = {};
        for (int d = 0; d < 144; d++) {
            float a[4], bv[8];
            *(float4*)a      = *(const float4*)&Qs[d*64 + ty*4];
            *(float4*)bv     = *(const float4*)&Ks[d*128 + tx*8];
            *(float4*)(bv+4) = *(const float4*)&Ks[d*128 + tx*8 + 4];
            #pragma unroll
            for (int i = 0; i < 4; i++)
                #pragma unroll
                for (int j = 0; j < 8; j++) acc[i][j] += a[i]*bv[j];
        }
        #pragma unroll
        for (int i = 0; i < 4; i++)
            #pragma unroll
            for (int j = 0; j < 8; j++)
                Ss[(ty*4+i)*132 + tx*8 + j] = acc[i][j] * (1.0f/12.0f);
    }
    __syncthreads();

    if (tid < 64) {
        float* r = Ss + tid*132;
        float mx = -1e30f;
        for (int k = 0; k < 128; k++) mx = fmaxf(mx, r[k]);
        float sum = 0.f;
        for (int k = 0; k < 128; k++) { float ev = expf(r[k]-mx); r[k] = ev; sum += ev; }
        float inv = 1.0f / sum;
        for (int k = 0; k < 128; k++) r[k] *= inv;
    }
    __syncthreads();

    {
        float o[4][9] = {};
        for (int k = 0; k < 128; k++) {
            float s[4];
            #pragma unroll
            for (int i = 0; i < 4; i++) s[i] = Ss[(ty*4+i)*132 + k];
            #pragma unroll
            for (int j = 0; j < 9; j++) {
                float vv = Vs[k*148 + tx*9 + j];
                #pragma unroll
                for (int i = 0; i < 4; i++) o[i][j] += s[i]*vv;
            }
        }
        #pragma unroll
        for (int i = 0; i < 4; i++)
            #pragma unroll
            for (int j = 0; j < 9; j++) {
                float v = o[i][j];
                __half hh = __float2half_rn(v);
                __half ll = __float2half_rn(v - __half2float(hh));
                long long off = (qrow0 + ty*4 + i)*DM + hc + tx*9 + j;
                Oh[off] = hh;
                Ol[off] = ll;
            }
    }
}

// ---------------- small exact kernels ----------------
__global__ void gate4(const float* __restrict__ A, const float* __restrict__ W,
                      const float* __restrict__ b, float* __restrict__ out)
{
    int w = blockIdx.x*8 + (threadIdx.x >> 5);
    int lane = threadIdx.x & 31;
    if (w >= NROW) return;
    const float* a = A + (long long)w*DM;
    float s0=0,s1=0,s2=0,s3=0;
    for (int c = lane*4; c < DM; c += 128) {
        float4 av = *(const float4*)(a + c);
        float4 w0 = *(const float4*)(W + c);
        float4 w1 = *(const float4*)(W + DM + c);
        float4 w2 = *(const float4*)(W + 2*DM + c);
        float4 w3 = *(const float4*)(W + 3*DM + c);
        s0 += av.x*w0.x + av.y*w0.y + av.z*w0.z + av.w*w0.w;
        s1 += av.x*w1.x + av.y*w1.y + av.z*w1.z + av.w*w1.w;
        s2 += av.x*w2.x + av.y*w2.y + av.z*w2.z + av.w*w2.w;
        s3 += av.x*w3.x + av.y*w3.y + av.z*w3.z + av.w*w3.w;
    }
    #pragma unroll
    for (int o = 16; o > 0; o >>= 1) {
        s0 += __shfl_xor_sync(0xffffffffu, s0, o);
        s1 += __shfl_xor_sync(0xffffffffu, s1, o);
        s2 += __shfl_xor_sync(0xffffffffu, s2, o);
        s3 += __shfl_xor_sync(0xffffffffu, s3, o);
    }
    if (lane == 0) {
        out[w*4+0] = s0 + b[0]; out[w*4+1] = s1 + b[1];
        out[w*4+2] = s2 + b[2]; out[w*4+3] = s3 + b[3];
    }
}

__global__ void hlk(const float* __restrict__ t, const float* __restrict__ w,
                    const float* __restrict__ bb, float* __restrict__ hl)
{
    int wi = threadIdx.x >> 5, lane = threadIdx.x & 31;
    int r = wi >> 1, o = wi & 1;
    const float* a = t + r*DM;
    const float* ww = w + o*DM;
    float s = 0.f;
    for (int c = lane*4; c < DM; c += 128) {
        float4 av = *(const float4*)(a + c);
        float4 wv = *(const float4*)(ww + c);
        s += av.x*wv.x + av.y*wv.y + av.z*wv.z + av.w*wv.w;
    }
    #pragma unroll
    for (int off = 16; off > 0; off >>= 1) s += __shfl_xor_sync(0xffffffffu, s, off);
    if (lane == 0) hl[r*2+o] = s + bb[o];
}

// ---------------- routing: gating + counts + offsets + scatter, one block ---
__global__ void route_all(const float* __restrict__ caplog, const float* __restrict__ aclog)
{
    __shared__ int scnt[8], scur[8];
    const int t = threadIdx.x;   // 1024 threads
    if (t < 8) scnt[t] = 0;
    __syncthreads();

    uint32_t k1a,k1b,k2a,k2b,k3a,k3b;
    tf2x32(0u, 42u, 0u, 0u, k1a, k1b);
    tf2x32(0u, 42u, 0u, 1u, k2a, k2b);
    tf2x32(0u, 42u, 0u, 2u, k3a, k3b);

    for (int n = t; n < NROW; n += 1024) {
        float g0 = gumbel_from_bits(jax_bits_p(k1a, k1b, 2u*(uint32_t)n + 0u));
        float g1 = gumbel_from_bits(jax_bits_p(k1a, k1b, 2u*(uint32_t)n + 1u));
        int bb = n >> 10;
        float l0 = g_hl[2*bb + 0] + g0;
        float l1 = g_hl[2*bb + 1] + g1;
        float mx = fmaxf(l0, l1);
        float e0 = expf(l0 - mx), e1 = expf(l1 - mx);
        float inv = 1.0f / (e0 + e1);
        g_cm[n] = e0 * inv;
        g_am[n] = e1 * inv;

        int be = 0; float bv = -1e30f;
        #pragma unroll
        for (int c = 0; c < 4; c++) {
            float g = gumbel_from_bits(jax_bits_p(k2a, k2b, 4u*(uint32_t)n + (uint32_t)c));
            float yv = caplog[n*4 + c] + g;
            if (yv > bv) { bv = yv; be = c; }
        }
        g_cpe[n] = be;
        atomicAdd(&scnt[be], 1);

        int ae = 0; bv = -1e30f;
        #pragma unroll
        for (int c = 0; c < 4; c++) {
            float g = gumbel_from_bits(jax_bits_p(k3a, k3b, 4u*(uint32_t)n + (uint32_t)c));
            float yv = aclog[n*4 + c] + g;
            if (yv > bv) { bv = yv; ae = c; }
        }
        g_ape[n] = ae;
        atomicAdd(&scnt[4 + ae], 1);
    }
    __syncthreads();

    if (t == 0) {
        int o = 0;
        for (int e2 = 0; e2 < 4; e2++) { g_off[e2] = o; scur[e2] = o; g_cnt[e2] = scnt[e2]; o += scnt[e2]; }
        o = NROW;
        for (int e2 = 4; e2 < 8; e2++) { g_off[e2] = o; scur[e2] = o; g_cnt[e2] = scnt[e2]; o += scnt[e2]; }
    }
    __syncthreads();

    for (int n = t; n < NROW; n += 1024) {
        int p = atomicAdd(&scur[g_cpe[n]], 1);
        g_idx[p] = n;
        p = atomicAdd(&scur[4 + g_ape[n]], 1);
        g_idx[p] = n;
    }
}

// ---------------- lb loss ----------------
__global__ void lb_kernel(float* __restrict__ outp, long long i1)
{
    __shared__ float sh[256 * 9];
    int t = threadIdx.x;
    float u[8] = {0,0,0,0,0,0,0,0};
    float ms = 0.f;
    for (int n = t; n < NROW; n += 256) {
        u[g_cpe[n]]     += g_cm[n];
        u[4 + g_ape[n]] += g_am[n];
        ms += g_cm[n] + g_am[n];
    }
    #pragma unroll
    for (int j = 0; j < 8; j++) sh[t*9 + j] = u[j];
    sh[t*9 + 8] = ms;
    __syncthreads();
    for (int stride = 128; stride > 0; stride >>= 1) {
        if (t < stride)
            #pragma unroll
            for (int j = 0; j < 9; j++) sh[t*9 + j] += sh[(t + stride)*9 + j];
        __syncthreads();
    }
    if (t == 0 && i1 >= 0) {
        float denom = 4.0f * sh[8] + 1e-10f;
        float acc = 0.f;
        for (int j = 0; j < 8; j++) {
            float uu = sh[j] / denom;
            acc += uu * logf(uu + 1e-10f);
        }
        outp[i1] = acc / 8.0f;
    }
}

// ---------------- host launcher ----------------
static inline void cvtA(const float* src, __half* h, __half* l, long long n)
{
    int n4 = (int)(n / 4);
    cvt_a16<<<(n4 + 255)/256, 256>>>((const float4*)src, (uint2*)h, (uint2*)l, n4);
}
static inline void cvtW(const float* src, __half* d, long long n)
{
    int n4 = (int)(n / 4);
    cvt_w16<<<(n4 + 255)/256, 256>>>((const float4*)src, (uint2*)d, n4);
}

extern "C" void kernel_launch(void* const* d_in, const int* in_sizes, int n_in,
                              void* d_out, int out_size)
{
    const float* x        = (const float*)d_in[0];
    const float* timei    = (const float*)d_in[1];
    const float* caption  = (const float*)d_in[2];
    const float* acoustic = (const float*)d_in[3];
    const float* w_in     = (const float*)d_in[4];
    const float* b_in     = (const float*)d_in[5];
    const float* w_out    = (const float*)d_in[6];
    const float* b_out    = (const float*)d_in[7];
    const float* hlw      = (const float*)d_in[8];
    const float* hlb      = (const float*)d_in[9];
    const float* cgw      = (const float*)d_in[10];
    const float* cgb      = (const float*)d_in[11];
    const float* agw      = (const float*)d_in[12];
    const float* agb      = (const float*)d_in[13];
    const float* cw1      = (const float*)d_in[14];
    const float* cw2      = (const float*)d_in[15];
    const float* cw3      = (const float*)d_in[16];
    const float* aw1      = (const float*)d_in[17];
    const float* aw2      = (const float*)d_in[18];
    const float* aw3      = (const float*)d_in[19];
    const float* fw1      = (const float*)d_in[20];
    const float* fw2      = (const float*)d_in[21];
    const float* fw3      = (const float*)d_in[22];
    float* out = (float*)d_out;

    float *pq,*pkv,*pcap2,*pclog,*palog,*phl,*pcm,*pam,*pH,*pR,*py;
    int *pidx,*poff,*pcnt;
    __half *xh,*xl,*gxh,*gxl,*cph,*cpl,*win16,*wout16,*ew16,*cah,*cal,*Hh,*Hl,*yh,*yl,*Rh,*Rl;

    cudaGetSymbolAddress((void**)&pq,    g_q);
    cudaGetSymbolAddress((void**)&pkv,   g_kv);
    cudaGetSymbolAddress((void**)&pcap2, g_cap2);
    cudaGetSymbolAddress((void**)&pclog, g_caplog);
    cudaGetSymbolAddress((void**)&palog, g_aclog);
    cudaGetSymbolAddress((void**)&phl,   g_hl);
    cudaGetSymbolAddress((void**)&pcm,   g_cm);
    cudaGetSymbolAddress((void**)&pam,   g_am);
    cudaGetSymbolAddress((void**)&pH,    g_H);
    cudaGetSymbolAddress((void**)&pR,    g_R);
    cudaGetSymbolAddress((void**)&py,    g_y);
    cudaGetSymbolAddress((void**)&pidx,  g_idx);
    cudaGetSymbolAddress((void**)&poff,  g_off);
    cudaGetSymbolAddress((void**)&pcnt,  g_cnt);
    cudaGetSymbolAddress((void**)&xh,    g_xh);
    cudaGetSymbolAddress((void**)&xl,    g_xl);
    cudaGetSymbolAddress((void**)&gxh,   g_gxh);
    cudaGetSymbolAddress((void**)&gxl,   g_gxl);
    cudaGetSymbolAddress((void**)&cph,   g_caph);
    cudaGetSymbolAddress((void**)&cpl,   g_capl);
    cudaGetSymbolAddress((void**)&win16, g_win16);
    cudaGetSymbolAddress((void**)&wout16,g_wout16);
    cudaGetSymbolAddress((void**)&ew16,  g_ew16);
    cudaGetSymbolAddress((void**)&cah,   g_cah);
    cudaGetSymbolAddress((void**)&cal,   g_cal);
    cudaGetSymbolAddress((void**)&Hh,    g_Hh);
    cudaGetSymbolAddress((void**)&Hl,    g_Hl);
    cudaGetSymbolAddress((void**)&yh,    g_yh);
    cudaGetSymbolAddress((void**)&yl,    g_yl);
    cudaGetSymbolAddress((void**)&Rh,    g_Rh);
    cudaGetSymbolAddress((void**)&Rl,    g_Rl);

    cudaFuncSetAttribute(attn2, cudaFuncAttributeMaxDynamicSharedMemorySize, SMEM_ATTN);
    cudaFuncSetAttribute(gemm_cp<0,0,0>, cudaFuncAttributeMaxDynamicSharedMemorySize, GSM_SIZE);
    cudaFuncSetAttribute(gemm_cp<2,0,0>, cudaFuncAttributeMaxDynamicSharedMemorySize, GSM_SIZE);
    cudaFuncSetAttribute(gemm_cp<2,1,1>, cudaFuncAttributeMaxDynamicSharedMemorySize, GSM_SIZE);
    cudaFuncSetAttribute(gemm_cp<2,1,3>, cudaFuncAttributeMaxDynamicSharedMemorySize, GSM_SIZE);

    const int n4per = HDM/4;

    cvtA(x, xh, xl, (long long)NROW*DM);
    cvtW(w_in, win16, 3LL*DM*DM);
    cvtA(caption, cph, cpl, (long long)SKV*DM);
    // Q (profiled slot #4)
    gemm_cp<0,0,0><<<dim3(9,16,1),512,GSM_SIZE>>>(xh, xl, DM, 0, win16, DM, 0, b_in,
        pq, DM, 0, nullptr,nullptr,nullptr,0, nullptr, nullptr, nullptr, NROW, DM, DM);
    // K|V merged (N = 2304)
    gemm_cp<0,0,0><<<dim3(18,2,1),512,GSM_SIZE>>>(cph, cpl, DM, 0, win16 + (long long)DM*DM, DM, 0, b_in + DM,
        pkv, KVLD, 0, nullptr,nullptr,nullptr,0, nullptr, nullptr, nullptr, SKV, KVLD, DM);
    cvtW(w_out, wout16, (long long)DM*DM);
    // attention -> fp16 hi/lo directly
    attn2<<<dim3(16,8,2),256,SMEM_ATTN>>>(pq, pkv, cah, cal);
    // out proj
    gemm_cp<0,0,0><<<dim3(9,16,1),512,GSM_SIZE>>>(cah, cal, DM, 0, wout16, DM, 0, b_out,
        pcap2, DM, 0, nullptr,nullptr,nullptr,0, nullptr, nullptr, nullptr, NROW, DM, DM);
    // hl + gate logits (exact fp32)
    hlk<<<1,128>>>(timei, hlw, hlb, phl);
    gate4<<<NROW/8,256>>>(pcap2, cgw, cgb, pclog);
    gate4<<<NROW/8,256>>>(acoustic, agw, agb, palog);
    // gating + routing (one block)
    route_all<<<1,1024>>>(pclog, palog);
    // expert weight conversions into slots
    dim3 pg((n4per + 255)/256, 1, 4);
    cvt_pair16<<<pg,256>>>((const float4*)cw1, (const float4*)cw3, (uint2*)(ew16 + 0LL*HDM),  n4per);
    cvt_pair16<<<pg,256>>>((const float4*)aw1, (const float4*)aw3, (uint2*)(ew16 + 8LL*HDM),  n4per);
    cvtW(cw2, ew16 + 16LL*HDM, 4LL*HDM);
    cvtW(aw2, ew16 + 20LL*HDM, 4LL*HDM);
    cvt_pair16<<<pg,256>>>((const float4*)fw1, (const float4*)fw3, (uint2*)(ew16 + 24LL*HDM), n4per);
    cvtW(fw2, ew16 + 32LL*HDM, 4LL*HDM);
    // permute x rows into bucket order
    permute_x<<<2*NROW,128>>>((const uint4*)xh, (const uint4*)xl, (uint4*)gxh, (uint4*)gxl);
    // MoE up: one GEMM, z=8 buckets, N=1536 (h1|h3)
    gemm_cp<2,0,0><<<dim3(12,16,8),512,GSM_SIZE>>>(gxh, gxl, DM, 0,
        ew16, DM, 2LL*HDM, nullptr,
        pH, 1536, 0, nullptr, poff, pcnt, 0, nullptr, nullptr, nullptr, NROW, 1536, DM);
    silumul_pair16<<<(4096*192 + 255)/256,256>>>((const float4*)pH, (uint2*)Hh, (uint2*)Hl, 4096*192);
    // MoE down cap / ac (ac emits yh/yl split in epilogue)
    gemm_cp<2,1,1><<<dim3(9,16,4),512,GSM_SIZE>>>(Hh, Hl, HIDN, 0,
        ew16 + 16LL*HDM, HIDN, (long long)HDM, nullptr,
        py, DM, 0, pidx, poff, pcnt, 0, pcm, nullptr, nullptr, NROW, DM, HIDN);
    gemm_cp<2,1,3><<<dim3(9,16,4),512,GSM_SIZE>>>(Hh, Hl, HIDN, 0,
        ew16 + 20LL*HDM, HIDN, (long long)HDM, nullptr,
        py, DM, 0, pidx, poff, pcnt, 4, pam, yh, yl, NROW, DM, HIDN);
    // region FF
    gemm_cp<0,0,0><<<dim3(12,16,4),512,GSM_SIZE>>>(yh, yl, DM, REG,
        ew16 + 24LL*HDM, DM, 2LL*HDM + REG, nullptr,
        pR, 1536, 2048LL*1536, nullptr,nullptr,nullptr,0, nullptr, nullptr, nullptr, NROW, 1536, REG);
    silumul_pair16<<<(8192*192 + 255)/256,256>>>((const float4*)pR, (uint2*)Rh, (uint2*)Rl, 8192*192);
    gemm_cp<0,0,0><<<dim3(3,16,4),512,GSM_SIZE>>>(Rh, Rl, HIDN, 2048LL*HIDN,
        ew16 + 32LL*HDM, HIDN, (long long)HDM + (long long)REG*HIDN, nullptr,
        out, DM, REG, nullptr,nullptr,nullptr,0, nullptr, nullptr, nullptr, NROW, REG, HIDN);
    // lb loss scalar
    long long zElems = (long long)NROW * DM;
    long long i1 = ((long long)out_size > zElems) ? zElems : -1;
    lb_kernel<<<1,256>>>(out, i1);
}